// round 1
// baseline (speedup 1.0000x reference)
#include <cuda_runtime.h>
#include <math.h>

#define BB 8
#define TT 256
#define VV 32
#define DD 256

// Scratch accumulators (no cudaMalloc allowed)
__device__ float g_ap[BB * TT];   // sum over (v,q) of exp(scores[i,i,v,q,k]) -> indexed [i,k]
__device__ float g_neg[BB * TT];  // sum over (j!=i,v,k) of exp(scores[i,j,v,q,k]) -> indexed [i,q]

__global__ void init_kernel() {
    int t = blockIdx.x * blockDim.x + threadIdx.x;
    if (t < BB * TT) { g_ap[t] = 0.0f; g_neg[t] = 0.0f; }
}

// One CTA: 64(q) x 64(k) tile of one (i,j,v) pair GEMM over D=256, then exp + reduce.
// blockIdx.y = pair index p: v = p & 31, j = (p>>5) & 7, i = p>>8
// blockIdx.x = tile index: qtile = x & 3, ktile = x >> 2
__global__ __launch_bounds__(256) void pair_kernel(const float* __restrict__ f,
                                                   const float* __restrict__ fa) {
    const int p = blockIdx.y;
    const int v = p & 31;
    const int ij = p >> 5;
    const int j = ij & 7;
    const int i = ij >> 3;
    const int q0 = (blockIdx.x & 3) * 64;
    const int k0 = (blockIdx.x >> 2) * 64;

    __shared__ float As[16][68];  // [d_chunk][q] ; pad 68 keeps float4 loads 16B-aligned
    __shared__ float Bs[16][68];  // [d_chunk][k]
    __shared__ float red[64];

    const int tid = threadIdx.x;
    const int tx = tid & 15;   // k quad
    const int ty = tid >> 4;   // q quad

    float acc[4][4];
#pragma unroll
    for (int a = 0; a < 4; a++)
#pragma unroll
        for (int b = 0; b < 4; b++) acc[a][b] = 0.0f;

    // layout [B,T,V,D]: f[i,v,q,d] = feature[((i*T+q)*V+v)*D + d]
    const size_t rs = (size_t)VV * DD;  // stride between consecutive q (or k)
    const float* fA = f  + ((size_t)(i * TT + q0) * VV + v) * DD;
    const float* fB = fa + ((size_t)(j * TT + k0) * VV + v) * DD;

    const int lrow = tid >> 2;        // 0..63 : row within tile
    const int lseg = (tid & 3) * 4;   // 0,4,8,12 : d offset within 16-chunk

    for (int d0 = 0; d0 < DD; d0 += 16) {
        float4 a4 = *(const float4*)(fA + (size_t)lrow * rs + d0 + lseg);
        float4 b4 = *(const float4*)(fB + (size_t)lrow * rs + d0 + lseg);
        __syncthreads();
        As[lseg + 0][lrow] = a4.x; As[lseg + 1][lrow] = a4.y;
        As[lseg + 2][lrow] = a4.z; As[lseg + 3][lrow] = a4.w;
        Bs[lseg + 0][lrow] = b4.x; Bs[lseg + 1][lrow] = b4.y;
        Bs[lseg + 2][lrow] = b4.z; Bs[lseg + 3][lrow] = b4.w;
        __syncthreads();
#pragma unroll
        for (int dc = 0; dc < 16; dc++) {
            float4 av = *(const float4*)&As[dc][ty * 4];
            float4 bv = *(const float4*)&Bs[dc][tx * 4];
            float a[4] = {av.x, av.y, av.z, av.w};
            float b[4] = {bv.x, bv.y, bv.z, bv.w};
#pragma unroll
            for (int qi = 0; qi < 4; qi++)
#pragma unroll
                for (int ki = 0; ki < 4; ki++) acc[qi][ki] = fmaf(a[qi], b[ki], acc[qi][ki]);
        }
    }

    // exp
    float e[4][4];
#pragma unroll
    for (int qi = 0; qi < 4; qi++)
#pragma unroll
        for (int ki = 0; ki < 4; ki++) e[qi][ki] = __expf(acc[qi][ki]);

    if (tid < 64) red[tid] = 0.0f;
    __syncthreads();

    if (i == j) {
        // positive pairs: sum over q per k -> g_ap[i, k]
#pragma unroll
        for (int ki = 0; ki < 4; ki++) {
            float s = e[0][ki] + e[1][ki] + e[2][ki] + e[3][ki];
            atomicAdd(&red[tx * 4 + ki], s);
        }
        __syncthreads();
        if (tid < 64) atomicAdd(&g_ap[i * TT + k0 + tid], red[tid]);
    } else {
        // negatives: sum over k per q -> g_neg[i, q]
#pragma unroll
        for (int qi = 0; qi < 4; qi++) {
            float s = e[qi][0] + e[qi][1] + e[qi][2] + e[qi][3];
            atomicAdd(&red[ty * 4 + qi], s);
        }
        __syncthreads();
        if (tid < 64) atomicAdd(&g_neg[i * TT + q0 + tid], red[tid]);
    }
}

__global__ void finalize_kernel(float* __restrict__ out) {
    __shared__ float sred[256];
    const int tid = threadIdx.x;
    float s = 0.0f;
    for (int idx = tid; idx < BB * TT; idx += 256) {
        s += logf(g_neg[idx]) - logf(g_ap[idx]);
    }
    sred[tid] = s;
    __syncthreads();
    for (int o = 128; o > 0; o >>= 1) {
        if (tid < o) sred[tid] += sred[tid + o];
        __syncthreads();
    }
    if (tid == 0) out[0] = sred[0] / (float)TT;
}

extern "C" void kernel_launch(void* const* d_in, const int* in_sizes, int n_in,
                              void* d_out, int out_size) {
    const float* feature     = (const float*)d_in[0];
    const float* feature_aug = (const float*)d_in[1];
    (void)in_sizes; (void)n_in; (void)out_size;

    init_kernel<<<(BB * TT + 255) / 256, 256>>>();

    dim3 grid(16, BB * BB * VV);  // 16 tiles x 2048 (i,j,v) pairs
    pair_kernel<<<grid, 256>>>(feature, feature_aug);

    finalize_kernel<<<1, 256>>>((float*)d_out);
}

// round 4
// speedup vs baseline: 8.3200x; 8.3200x over previous
#include <cuda_runtime.h>
#include <cuda_bf16.h>
#include <cstdint>
#include <math.h>

#define BB 8
#define TT 256
#define VV 32
#define DD 256
#define NELEM (BB * TT * VV * DD)

// ---------------- scratch (no cudaMalloc allowed) ----------------
__device__ float g_ap[BB * TT];   // [i,k]
__device__ float g_neg[BB * TT];  // [i,q]
__device__ __nv_bfloat16 g_fbf[NELEM];   // feature     as [B][V][T][D] bf16
__device__ __nv_bfloat16 g_fabf[NELEM];  // feature_aug as [B][V][T][D] bf16

__device__ __forceinline__ uint32_t smem_to_u32(const void* p) {
    uint32_t a;
    asm("{ .reg .u64 t; cvta.to.shared.u64 t, %1; cvt.u32.u64 %0, t; }" : "=r"(a) : "l"(p));
    return a;
}

#define CP_ASYNC16(dst, src) \
    asm volatile("cp.async.cg.shared.global [%0], [%1], 16;" :: "r"(dst), "l"(src) : "memory")
#define CP_COMMIT() asm volatile("cp.async.commit_group;" ::: "memory")
#define CP_WAIT(n)  asm volatile("cp.async.wait_group %0;" :: "n"(n) : "memory")

#define LDMATRIX_X4(r0, r1, r2, r3, addr) \
    asm volatile("ldmatrix.sync.aligned.m8n8.x4.shared.b16 {%0,%1,%2,%3}, [%4];" \
                 : "=r"(r0), "=r"(r1), "=r"(r2), "=r"(r3) : "r"(addr))

#define MMA16816(c, a0, a1, a2, a3, b0, b1) \
    asm volatile("mma.sync.aligned.m16n8k16.row.col.f32.bf16.bf16.f32 " \
                 "{%0,%1,%2,%3}, {%4,%5,%6,%7}, {%8,%9}, {%0,%1,%2,%3};" \
                 : "+f"((c)[0]), "+f"((c)[1]), "+f"((c)[2]), "+f"((c)[3]) \
                 : "r"(a0), "r"(a1), "r"(a2), "r"(a3), "r"(b0), "r"(b1))

// SMEM: 2 stages; stage s: A at s*32768 (128 rows x 128B), B at s*32768+16384
#define A_OFF(s) ((s) * 32768)
#define B_OFF(s) ((s) * 32768 + 16384)
#define SMEM_DYN 65536

// ---------------- kernels ----------------
__global__ void init_kernel() {
    int t = blockIdx.x * blockDim.x + threadIdx.x;
    if (t < BB * TT) { g_ap[t] = 0.0f; g_neg[t] = 0.0f; }
}

// fp32 [B][T][V][D] -> bf16 [B][V][T][D]
__global__ __launch_bounds__(256) void convert_kernel(const float* __restrict__ f,
                                                      const float* __restrict__ fa) {
    const float* src = (blockIdx.y == 0) ? f : fa;
    __nv_bfloat16* dst = (blockIdx.y == 0) ? g_fbf : g_fabf;
    long long e = ((long long)blockIdx.x * 256 + threadIdx.x) * 4;
    if (e >= NELEM) return;
    int d = (int)(e & 255);
    long long r = e >> 8;
    int v = (int)(r & 31);
    r >>= 5;
    int t = (int)(r & 255);
    int b = (int)(r >> 8);
    float4 x = *(const float4*)(src + e);
    __nv_bfloat162 lo = __floats2bfloat162_rn(x.x, x.y);
    __nv_bfloat162 hi = __floats2bfloat162_rn(x.z, x.w);
    long long o = (((long long)(b * VV + v) * TT + t) * DD + d);
    *(__nv_bfloat162*)(dst + o)     = lo;
    *(__nv_bfloat162*)(dst + o + 2) = hi;
}

// One CTA: 128(M) x 128(N) x 256(K) tile of one (i,j,v) pair + fused exp/row-sum.
// blockIdx.y = pair p: i=p>>8, j=(p>>5)&7, v=p&31.
// blockIdx.x: mtile = x&1, ntile = x>>1.
// off-diag: A = f[i,v] rows q (M), B = fa[j,v] rows k (N) -> row-sum -> g_neg[i,q]
// diag    : A = fa[i,v] rows k (M), B = f[i,v] rows q (N) -> row-sum -> g_ap[i,k]
__global__ __launch_bounds__(256) void pair_mma_kernel() {
    extern __shared__ char smem[];
    __shared__ float red[128];
    const uint32_t smem_base = smem_to_u32(smem);

    const int tid  = threadIdx.x;
    const int lane = tid & 31;
    const int wid  = tid >> 5;
    const int warp_m = wid & 1;   // 2 warp rows (64 M each)
    const int warp_n = wid >> 1;  // 4 warp cols (32 N each)

    const int p = blockIdx.y;
    const int v = p & 31;
    const int j = (p >> 5) & 7;
    const int i = p >> 8;
    const int mtile = blockIdx.x & 1;
    const int ntile = blockIdx.x >> 1;
    const bool diag = (i == j);

    const __nv_bfloat16* Apg = (diag ? g_fabf : g_fbf)
        + ((long long)(i * VV + v) * TT + mtile * 128) * DD;
    const __nv_bfloat16* Bpg = (diag ? g_fbf : g_fabf)
        + ((long long)((diag ? i : j) * VV + v) * TT + ntile * 128) * DD;

    if (tid < 128) red[tid] = 0.0f;

    // per-thread cp.async assignment: 2048 x 16B per stage, 8 per thread
    // idx<1024: A(row=idx>>3, seg=idx&7); else B
    // compute k-chunks of 64 (4 chunks), double buffered
    float c[4][4][4];
#pragma unroll
    for (int mi = 0; mi < 4; mi++)
#pragma unroll
        for (int ni = 0; ni < 4; ni++)
#pragma unroll
            for (int e = 0; e < 4; e++) c[mi][ni][e] = 0.0f;

    // ldmatrix lane addressing (row within 16-row tile, swizzled seg)
    const int l15 = lane & 15;
    const int l7  = lane & 7;
    const int lhi = lane >> 4;  // 0/1 -> +16B within 32B k16 window
    const uint32_t a_lane_base = smem_base + (warp_m * 64 + l15) * 128;
    const uint32_t b_lane_base = smem_base + (warp_n * 32 + l15) * 128;

    // prologue: stage 0 (chunk 0)
    {
#pragma unroll
        for (int t = 0; t < 8; t++) {
            int idx = tid + t * 256;
            int li  = idx & 1023;
            int row = li >> 3, seg = li & 7;
            const __nv_bfloat16* src = (idx < 1024 ? Apg : Bpg) + row * DD + seg * 8;
            uint32_t dst = smem_base + (idx < 1024 ? A_OFF(0) : B_OFF(0))
                           + row * 128 + ((seg ^ (row & 7)) << 4);
            CP_ASYNC16(dst, src);
        }
        CP_COMMIT();
    }

    for (int ch = 0; ch < 4; ch++) {
        const int s = ch & 1;
        if (ch < 3) {
            const int d0 = (ch + 1) * 64;
            const int s2 = (ch + 1) & 1;
#pragma unroll
            for (int t = 0; t < 8; t++) {
                int idx = tid + t * 256;
                int li  = idx & 1023;
                int row = li >> 3, seg = li & 7;
                const __nv_bfloat16* src = (idx < 1024 ? Apg : Bpg) + row * DD + d0 + seg * 8;
                uint32_t dst = smem_base + (idx < 1024 ? A_OFF(s2) : B_OFF(s2))
                               + row * 128 + ((seg ^ (row & 7)) << 4);
                CP_ASYNC16(dst, src);
            }
            CP_COMMIT();
            CP_WAIT(1);
        } else {
            CP_WAIT(0);
        }
        __syncthreads();

        const uint32_t abase = a_lane_base + A_OFF(s);
        const uint32_t bbase = b_lane_base + B_OFF(s);
#pragma unroll
        for (int kk = 0; kk < 4; kk++) {
            const uint32_t swz = ((uint32_t)((kk * 2 + lhi) ^ l7)) << 4;
            uint32_t a[4][4];
#pragma unroll
            for (int mi = 0; mi < 4; mi++) {
                LDMATRIX_X4(a[mi][0], a[mi][1], a[mi][2], a[mi][3],
                            abase + mi * 16 * 128 + swz);
            }
            uint32_t b[4][2];
#pragma unroll
            for (int nb = 0; nb < 2; nb++) {
                uint32_t r0, r1, r2, r3;
                LDMATRIX_X4(r0, r1, r2, r3, bbase + nb * 16 * 128 + swz);
                b[nb * 2 + 0][0] = r0; b[nb * 2 + 0][1] = r2;
                b[nb * 2 + 1][0] = r1; b[nb * 2 + 1][1] = r3;
            }
#pragma unroll
            for (int mi = 0; mi < 4; mi++)
#pragma unroll
                for (int ni = 0; ni < 4; ni++)
                    MMA16816(c[mi][ni], a[mi][0], a[mi][1], a[mi][2], a[mi][3],
                             b[ni][0], b[ni][1]);
        }
        __syncthreads();
    }

    // epilogue: exp + row sums (rows = M dim)
#pragma unroll
    for (int mi = 0; mi < 4; mi++) {
        float s0 = 0.0f, s1 = 0.0f;
#pragma unroll
        for (int ni = 0; ni < 4; ni++) {
            s0 += __expf(c[mi][ni][0]) + __expf(c[mi][ni][1]);
            s1 += __expf(c[mi][ni][2]) + __expf(c[mi][ni][3]);
        }
        s0 += __shfl_xor_sync(0xFFFFFFFF, s0, 1);
        s0 += __shfl_xor_sync(0xFFFFFFFF, s0, 2);
        s1 += __shfl_xor_sync(0xFFFFFFFF, s1, 1);
        s1 += __shfl_xor_sync(0xFFFFFFFF, s1, 2);
        if ((lane & 3) == 0) {
            int r0 = warp_m * 64 + mi * 16 + (lane >> 2);
            atomicAdd(&red[r0], s0);
            atomicAdd(&red[r0 + 8], s1);
        }
    }
    __syncthreads();

    if (tid < 128) {
        int grow = mtile * 128 + tid;
        atomicAdd(diag ? &g_ap[i * TT + grow] : &g_neg[i * TT + grow], red[tid]);
    }
}

__global__ void finalize_kernel(float* __restrict__ out) {
    __shared__ float sred[256];
    const int tid = threadIdx.x;
    float s = 0.0f;
    for (int idx = tid; idx < BB * TT; idx += 256) {
        s += logf(g_neg[idx]) - logf(g_ap[idx]);
    }
    sred[tid] = s;
    __syncthreads();
    for (int o = 128; o > 0; o >>= 1) {
        if (tid < o) sred[tid] += sred[tid + o];
        __syncthreads();
    }
    if (tid == 0) out[0] = sred[0] / (float)TT;
}

extern "C" void kernel_launch(void* const* d_in, const int* in_sizes, int n_in,
                              void* d_out, int out_size) {
    const float* feature     = (const float*)d_in[0];
    const float* feature_aug = (const float*)d_in[1];
    (void)in_sizes; (void)n_in; (void)out_size;

    static int configured = 0;
    if (!configured) {
        cudaFuncSetAttribute(pair_mma_kernel,
                             cudaFuncAttributeMaxDynamicSharedMemorySize, SMEM_DYN);
        configured = 1;
    }

    init_kernel<<<(BB * TT + 255) / 256, 256>>>();

    dim3 cgrid((NELEM / 4 + 255) / 256, 2);
    convert_kernel<<<cgrid, 256>>>(feature, feature_aug);

    dim3 grid(4, BB * BB * VV);  // (mtile,ntile) x 2048 pairs
    pair_mma_kernel<<<grid, 256, SMEM_DYN>>>();

    finalize_kernel<<<1, 256>>>((float*)d_out);
}